// round 6
// baseline (speedup 1.0000x reference)
#include <cuda_runtime.h>

// GlimpseSensor: extract P=3 patches (sizes 64,128,256) centered at l, nearest-
// downsample each to 64x64. Pure gather, zero-fill out of bounds.
// Shapes fixed by setup_inputs: x (64,3,512,512) f32, l (64,2) f32,
// out (64,3,3,64,64) f32.

#define B_   64
#define C_   3
#define H_   512
#define W_   512
#define P_   3
#define DS_  64

// Each thread produces 4 consecutive output columns (float4 store).
// tid layout: tid = (((b*P + p)*C + c)*DS + r)*16 + j4   -> out float4 index = tid
static constexpr int TOTAL_VEC = B_ * P_ * C_ * DS_ * (DS_ / 4);  // 589,824

__global__ void __launch_bounds__(256) glimpse_kernel(
    const float* __restrict__ x,
    const float* __restrict__ l,
    float* __restrict__ out)
{
    int tid = blockIdx.x * blockDim.x + threadIdx.x;
    if (tid >= TOTAL_VEC) return;

    int j4 = tid & 15;            // which group of 4 columns
    int r  = (tid >> 4) & (DS_ - 1);
    int t2 = tid >> 10;           // (b*P + p)*C + c
    int c  = t2 % C_;
    int bp = t2 / C_;             // b*P + p
    int p  = bp % P_;
    int b  = bp / P_;

    int stride = 1 << p;          // size / ds
    int half   = 32 << p;         // size / 2

    float lr = l[2 * b];
    float lc = l[2 * b + 1];
    // match jnp.floor(0.5 * (l + 1.0) * H) exactly (fp32, same op order)
    int base_r = (int)floorf((0.5f * (lr + 1.0f)) * (float)H_) - half;
    int base_c = (int)floorf((0.5f * (lc + 1.0f)) * (float)H_) - half;

    int row = base_r + r * stride;
    bool rok = (row >= 0) & (row < H_);
    const float* __restrict__ xrow = x + (((size_t)(b * C_ + c) * H_ + (rok ? row : 0)) * W_);

    int j0 = j4 * 4;
    float4 v;
    {
        int col0 = base_c + (j0 + 0) * stride;
        int col1 = base_c + (j0 + 1) * stride;
        int col2 = base_c + (j0 + 2) * stride;
        int col3 = base_c + (j0 + 3) * stride;
        v.x = (rok && col0 >= 0 && col0 < W_) ? __ldg(xrow + col0) : 0.0f;
        v.y = (rok && col1 >= 0 && col1 < W_) ? __ldg(xrow + col1) : 0.0f;
        v.z = (rok && col2 >= 0 && col2 < W_) ? __ldg(xrow + col2) : 0.0f;
        v.w = (rok && col3 >= 0 && col3 < W_) ? __ldg(xrow + col3) : 0.0f;
    }

    reinterpret_cast<float4*>(out)[tid] = v;
}

extern "C" void kernel_launch(void* const* d_in, const int* in_sizes, int n_in,
                              void* d_out, int out_size)
{
    const float* x = (const float*)d_in[0];
    const float* l = (const float*)d_in[1];
    float* out = (float*)d_out;

    constexpr int threads = 256;
    constexpr int blocks = (TOTAL_VEC + threads - 1) / threads;  // 2304
    glimpse_kernel<<<blocks, threads>>>(x, l, out);
}

// round 10
// speedup vs baseline: 1.0993x; 1.0993x over previous
#include <cuda_runtime.h>

// GlimpseSensor: extract P=3 patches (sizes 64,128,256) centered at l, nearest-
// downsample each to 64x64. Pure gather, zero-fill out of bounds.
// Shapes fixed by setup_inputs: x (64,3,512,512) f32, l (64,2) f32,
// out (64,3,3,64,64) f32.
//
// Mapping (R6): adjacent lanes read adjacent input columns so warp-LDGs hit
// the minimal sector count per stride (5/9/17 sectors for p=0/1/2 instead of
// up to 32). Each thread handles 2 output columns: lane and lane+32.

#define B_   64
#define C_   3
#define H_   512
#define W_   512
#define P_   3
#define DS_  64

// threads: tid = ((((b*P + p)*C + c)*DS + r) * 32 + lane_col)
static constexpr int TOTAL_THREADS = B_ * P_ * C_ * DS_ * 32;  // 1,179,648

__global__ void __launch_bounds__(256) glimpse_kernel(
    const float* __restrict__ x,
    const float* __restrict__ l,
    float* __restrict__ out)
{
    int tid = blockIdx.x * blockDim.x + threadIdx.x;

    int col_lo = tid & 31;            // output col, low half (0..31)
    int r      = (tid >> 5) & (DS_ - 1);
    int t2     = tid >> 11;           // (b*P + p)*C + c
    int c      = t2 % C_;
    int bp     = t2 / C_;             // b*P + p
    int p      = bp % P_;
    int b      = bp / P_;

    int stride = 1 << p;              // size / ds
    int half   = 32 << p;             // size / 2

    float lr = l[2 * b];
    float lc = l[2 * b + 1];
    // match jnp.floor(0.5 * (l + 1.0) * H) exactly (fp32, same op order)
    int base_r = (int)floorf((0.5f * (lr + 1.0f)) * (float)H_) - half;
    int base_c = (int)floorf((0.5f * (lc + 1.0f)) * (float)H_) - half;

    int row = base_r + r * stride;
    bool rok = (row >= 0) & (row < H_);
    const float* __restrict__ xrow =
        x + (((size_t)(b * C_ + c) * H_ + (rok ? row : 0)) * W_);

    // two output columns per thread: col_lo and col_lo+32
    int icol0 = base_c + col_lo * stride;
    int icol1 = icol0 + 32 * stride;

    float v0 = (rok && icol0 >= 0 && icol0 < W_) ? __ldg(xrow + icol0) : 0.0f;
    float v1 = (rok && icol1 >= 0 && icol1 < W_) ? __ldg(xrow + icol1) : 0.0f;

    // out element index: ((t2*DS + r)*DS) + col
    int obase = ((t2 << 6) + r) << 6;   // t2*64*64 + r*64
    out[obase + col_lo]      = v0;
    out[obase + col_lo + 32] = v1;
}

extern "C" void kernel_launch(void* const* d_in, const int* in_sizes, int n_in,
                              void* d_out, int out_size)
{
    const float* x = (const float*)d_in[0];
    const float* l = (const float*)d_in[1];
    float* out = (float*)d_out;

    constexpr int threads = 256;
    constexpr int blocks = TOTAL_THREADS / threads;  // 4608
    glimpse_kernel<<<blocks, threads>>>(x, l, out);
}

// round 11
// speedup vs baseline: 1.1464x; 1.0429x over previous
#include <cuda_runtime.h>

// GlimpseSensor: extract P=3 patches (sizes 64,128,256) centered at l, nearest-
// downsample each to 64x64. Pure gather, zero-fill out of bounds.
// Shapes fixed by setup_inputs: x (64,3,512,512) f32, l (64,2) f32,
// out (64,3,3,64,64) f32.
//
// Mapping (R6): adjacent lanes read adjacent input columns so warp-LDGs hit
// the minimal sector count per stride (5/9/17 sectors for p=0/1/2 instead of
// up to 32). Each thread handles 2 output columns: lane and lane+32.

#define B_   64
#define C_   3
#define H_   512
#define W_   512
#define P_   3
#define DS_  64

// threads: tid = ((((b*P + p)*C + c)*DS + r) * 32 + lane_col)
static constexpr int TOTAL_THREADS = B_ * P_ * C_ * DS_ * 32;  // 1,179,648

__global__ void __launch_bounds__(256) glimpse_kernel(
    const float* __restrict__ x,
    const float* __restrict__ l,
    float* __restrict__ out)
{
    int tid = blockIdx.x * blockDim.x + threadIdx.x;

    int col_lo = tid & 31;            // output col, low half (0..31)
    int r      = (tid >> 5) & (DS_ - 1);
    int t2     = tid >> 11;           // (b*P + p)*C + c
    int c      = t2 % C_;
    int bp     = t2 / C_;             // b*P + p
    int p      = bp % P_;
    int b      = bp / P_;

    int stride = 1 << p;              // size / ds
    int half   = 32 << p;             // size / 2

    float lr = l[2 * b];
    float lc = l[2 * b + 1];
    // match jnp.floor(0.5 * (l + 1.0) * H) exactly (fp32, same op order)
    int base_r = (int)floorf((0.5f * (lr + 1.0f)) * (float)H_) - half;
    int base_c = (int)floorf((0.5f * (lc + 1.0f)) * (float)H_) - half;

    int row = base_r + r * stride;
    bool rok = (row >= 0) & (row < H_);
    const float* __restrict__ xrow =
        x + (((size_t)(b * C_ + c) * H_ + (rok ? row : 0)) * W_);

    // two output columns per thread: col_lo and col_lo+32
    int icol0 = base_c + col_lo * stride;
    int icol1 = icol0 + 32 * stride;

    float v0 = (rok && icol0 >= 0 && icol0 < W_) ? __ldg(xrow + icol0) : 0.0f;
    float v1 = (rok && icol1 >= 0 && icol1 < W_) ? __ldg(xrow + icol1) : 0.0f;

    // out element index: ((t2*DS + r)*DS) + col
    int obase = ((t2 << 6) + r) << 6;   // t2*64*64 + r*64
    out[obase + col_lo]      = v0;
    out[obase + col_lo + 32] = v1;
}

extern "C" void kernel_launch(void* const* d_in, const int* in_sizes, int n_in,
                              void* d_out, int out_size)
{
    const float* x = (const float*)d_in[0];
    const float* l = (const float*)d_in[1];
    float* out = (float*)d_out;

    constexpr int threads = 256;
    constexpr int blocks = TOTAL_THREADS / threads;  // 4608
    glimpse_kernel<<<blocks, threads>>>(x, l, out);
}

// round 12
// speedup vs baseline: 1.1505x; 1.0036x over previous
#include <cuda_runtime.h>

// GlimpseSensor: extract P=3 patches (sizes 64,128,256) centered at l, nearest-
// downsample each to 64x64. Pure gather, zero-fill out of bounds.
// Shapes fixed: x (64,3,512,512) f32, l (64,2) f32, out (64,3,3,64,64) f32.
//
// R11: latency-bound fix. Each thread produces 8 outputs (4 rows x 2 cols)
// with all 8 LDGs front-batched (MLP=8). Grid decode moved to blockIdx
// (z=b, y=p*C+c, x=row-group) so no per-thread div/mod. Lane-adjacent input
// columns keep warp loads at minimal sector counts (5/9/17 for p=0/1/2).

#define B_   64
#define C_   3
#define H_   512
#define W_   512
#define P_   3
#define DS_  64
#define ROWS_PER_THREAD 4

__global__ void __launch_bounds__(256) glimpse_kernel(
    const float* __restrict__ x,
    const float* __restrict__ l,
    float* __restrict__ out)
{
    const int lane = threadIdx.x & 31;
    const int w    = threadIdx.x >> 5;          // warp in block, 0..7
    const int b    = blockIdx.z;                // 0..63
    const int pc   = blockIdx.y;                // p*C + c, 0..8
    const int p    = pc / 3;                    // uniform per block
    const int c    = pc - 3 * p;

    const int stride = 1 << p;                  // size / ds
    const int half   = 32 << p;                 // size / 2

    const float lr = __ldg(&l[2 * b]);
    const float lc = __ldg(&l[2 * b + 1]);
    // match jnp.floor(0.5 * (l + 1.0) * H) exactly (fp32, same op order)
    const int base_r = (int)floorf((0.5f * (lr + 1.0f)) * (float)H_) - half;
    const int base_c = (int)floorf((0.5f * (lc + 1.0f)) * (float)H_) - half;

    // columns handled by this lane (loop-invariant across rows)
    const int icol0 = base_c + lane * stride;
    const int icol1 = icol0 + 32 * stride;
    const bool c0ok = (icol0 >= 0) & (icol0 < W_);
    const bool c1ok = (icol1 >= 0) & (icol1 < W_);

    const int r0 = blockIdx.x * 32 + w * ROWS_PER_THREAD;   // first output row
    const float* __restrict__ xplane = x + (size_t)(b * C_ + c) * (H_ * W_);

    float v0[ROWS_PER_THREAD], v1[ROWS_PER_THREAD];

    // ---- load phase: 8 independent LDGs, front-batched ----
    #pragma unroll
    for (int i = 0; i < ROWS_PER_THREAD; ++i) {
        int row = base_r + (r0 + i) * stride;
        bool rok = (row >= 0) & (row < H_);
        const float* __restrict__ xrow = xplane + (size_t)(rok ? row : 0) * W_;
        v0[i] = (rok & c0ok) ? __ldg(xrow + icol0) : 0.0f;
        v1[i] = (rok & c1ok) ? __ldg(xrow + icol1) : 0.0f;
    }

    // ---- store phase: fully coalesced ----
    // out element index: ((b*9 + pc)*64 + r)*64 + col
    const int t2 = b * 9 + pc;
    #pragma unroll
    for (int i = 0; i < ROWS_PER_THREAD; ++i) {
        int obase = (((t2 << 6) + (r0 + i)) << 6);
        out[obase + lane]      = v0[i];
        out[obase + lane + 32] = v1[i];
    }
}

extern "C" void kernel_launch(void* const* d_in, const int* in_sizes, int n_in,
                              void* d_out, int out_size)
{
    const float* x = (const float*)d_in[0];
    const float* l = (const float*)d_in[1];
    float* out = (float*)d_out;

    // grid: x = row-groups (64 rows / (8 warps * 4 rows) = 2), y = p*C+c, z = b
    dim3 grid(2, P_ * C_, B_);   // 1152 blocks
    glimpse_kernel<<<grid, 256>>>(x, l, out);
}

// round 13
// speedup vs baseline: 1.1845x; 1.0295x over previous
#include <cuda_runtime.h>

// GlimpseSensor: extract P=3 patches (sizes 64,128,256) centered at l, nearest-
// downsample each to 64x64. Pure gather, zero-fill out of bounds.
// Shapes fixed: x (64,3,512,512) f32, l (64,2) f32, out (64,3,3,64,64) f32.
//
// R11: latency-bound fix. Each thread produces 8 outputs (4 rows x 2 cols)
// with all 8 LDGs front-batched (MLP=8). Grid decode moved to blockIdx
// (z=b, y=p*C+c, x=row-group) so no per-thread div/mod. Lane-adjacent input
// columns keep warp loads at minimal sector counts (5/9/17 for p=0/1/2).

#define B_   64
#define C_   3
#define H_   512
#define W_   512
#define P_   3
#define DS_  64
#define ROWS_PER_THREAD 4

__global__ void __launch_bounds__(256) glimpse_kernel(
    const float* __restrict__ x,
    const float* __restrict__ l,
    float* __restrict__ out)
{
    const int lane = threadIdx.x & 31;
    const int w    = threadIdx.x >> 5;          // warp in block, 0..7
    const int b    = blockIdx.z;                // 0..63
    const int pc   = blockIdx.y;                // p*C + c, 0..8
    const int p    = pc / 3;                    // uniform per block
    const int c    = pc - 3 * p;

    const int stride = 1 << p;                  // size / ds
    const int half   = 32 << p;                 // size / 2

    const float lr = __ldg(&l[2 * b]);
    const float lc = __ldg(&l[2 * b + 1]);
    // match jnp.floor(0.5 * (l + 1.0) * H) exactly (fp32, same op order)
    const int base_r = (int)floorf((0.5f * (lr + 1.0f)) * (float)H_) - half;
    const int base_c = (int)floorf((0.5f * (lc + 1.0f)) * (float)H_) - half;

    // columns handled by this lane (loop-invariant across rows)
    const int icol0 = base_c + lane * stride;
    const int icol1 = icol0 + 32 * stride;
    const bool c0ok = (icol0 >= 0) & (icol0 < W_);
    const bool c1ok = (icol1 >= 0) & (icol1 < W_);

    const int r0 = blockIdx.x * 32 + w * ROWS_PER_THREAD;   // first output row
    const float* __restrict__ xplane = x + (size_t)(b * C_ + c) * (H_ * W_);

    float v0[ROWS_PER_THREAD], v1[ROWS_PER_THREAD];

    // ---- load phase: 8 independent LDGs, front-batched ----
    #pragma unroll
    for (int i = 0; i < ROWS_PER_THREAD; ++i) {
        int row = base_r + (r0 + i) * stride;
        bool rok = (row >= 0) & (row < H_);
        const float* __restrict__ xrow = xplane + (size_t)(rok ? row : 0) * W_;
        v0[i] = (rok & c0ok) ? __ldg(xrow + icol0) : 0.0f;
        v1[i] = (rok & c1ok) ? __ldg(xrow + icol1) : 0.0f;
    }

    // ---- store phase: fully coalesced ----
    // out element index: ((b*9 + pc)*64 + r)*64 + col
    const int t2 = b * 9 + pc;
    #pragma unroll
    for (int i = 0; i < ROWS_PER_THREAD; ++i) {
        int obase = (((t2 << 6) + (r0 + i)) << 6);
        out[obase + lane]      = v0[i];
        out[obase + lane + 32] = v1[i];
    }
}

extern "C" void kernel_launch(void* const* d_in, const int* in_sizes, int n_in,
                              void* d_out, int out_size)
{
    const float* x = (const float*)d_in[0];
    const float* l = (const float*)d_in[1];
    float* out = (float*)d_out;

    // grid: x = row-groups (64 rows / (8 warps * 4 rows) = 2), y = p*C+c, z = b
    dim3 grid(2, P_ * C_, B_);   // 1152 blocks
    glimpse_kernel<<<grid, 256>>>(x, l, out);
}